// round 8
// baseline (speedup 1.0000x reference)
#include <cuda_runtime.h>
#include <cuda_fp16.h>

// SimpleGRU: B=2048, T=2048, H=32, scalar input.
// One warp = FOUR batch elements as two independent packed half2 streams
// ({A,B} and {C,D}); lane i = hidden unit i. Weights duplicated {w,w},
// shared by both streams. h broadcast by 32 warp shuffles per stream
// (no smem, no syncwarp). x-side folded into r/z chain inits.
// All loop math fp16 (HFMA2 rt2); sigmoid via tanh.approx.f16x2.

#define FULL_MASK 0xffffffffu

__device__ __forceinline__ __half2 htanh2(__half2 a) {
    unsigned int d, s = *reinterpret_cast<unsigned int*>(&a);
    asm("tanh.approx.f16x2 %0, %1;" : "=r"(d) : "r"(s));
    return *reinterpret_cast<__half2*>(&d);
}
__device__ __forceinline__ __half2 u2h(unsigned int u) {
    return *reinterpret_cast<const __half2*>(&u);
}
__device__ __forceinline__ unsigned int h2u(__half2 h) {
    return *reinterpret_cast<unsigned int*>(&h);
}

__global__ void __launch_bounds__(32)
gru_kernel(const float* __restrict__ x,
           const float* __restrict__ w_ih,
           const float* __restrict__ w_hh,
           const float* __restrict__ b_ih,
           const float* __restrict__ b_hh,
           const float* __restrict__ head_w,
           const float* __restrict__ head_b,
           float* __restrict__ out,
           int B, int T)
{
    const int b0 = blockIdx.x * 4;          // four batch elements per warp
    const int i  = threadIdx.x;             // lane == hidden unit, H == 32

    // Duplicated {w,w} W_hh rows for unit i; r,z prescaled by 0.5.
    __half2 wr[32], wz[32], wn[32];
    {
        const float* Wr = w_hh + (0  + i) * 32;
        const float* Wz = w_hh + (32 + i) * 32;
        const float* Wn = w_hh + (64 + i) * 32;
        #pragma unroll
        for (int j = 0; j < 32; j++) {
            wr[j] = __float2half2_rn(Wr[j] * 0.5f);
            wz[j] = __float2half2_rn(Wz[j] * 0.5f);
            wn[j] = __float2half2_rn(Wn[j]);
        }
    }

    // x-side constants, duplicated into both lanes.
    const __half2 wir2 = __float2half2_rn(w_ih[i]      * 0.5f);
    const __half2 cr2  = __float2half2_rn((b_ih[i]      + b_hh[i])      * 0.5f);
    const __half2 wiz2 = __float2half2_rn(w_ih[32 + i] * 0.5f);
    const __half2 cz2  = __float2half2_rn((b_ih[32 + i] + b_hh[32 + i]) * 0.5f);
    const __half2 win2 = __float2half2_rn(w_ih[64 + i]);
    const __half2 cnx2 = __float2half2_rn(b_ih[64 + i]);
    const __half2 cnh2 = __float2half2_rn(b_hh[64 + i]);
    const __half2 hlf2 = __float2half2_rn(0.5f);

    __half2 h2a = __float2half2_rn(0.0f);   // stream 1: {hA_i, hB_i}
    __half2 h2b = __float2half2_rn(0.0f);   // stream 2: {hC_i, hD_i}
    const float* xA = x + (long long)b0 * T;
    const float* xB = xA + T;
    const float* xC = xB + T;
    const float* xD = xC + T;

    for (int t0 = 0; t0 < T; t0 += 32) {
        unsigned int xpa = h2u(__floats2half2_rn(xA[t0 + i], xB[t0 + i]));
        unsigned int xpb = h2u(__floats2half2_rn(xC[t0 + i], xD[t0 + i]));
        #pragma unroll 2
        for (int k = 0; k < 32; k++) {
            __half2 xta = u2h(__shfl_sync(FULL_MASK, xpa, k));
            __half2 xtb = u2h(__shfl_sync(FULL_MASK, xpb, k));

            // Broadcast both packed h vectors via shuffles (no smem/sync).
            unsigned int hua = h2u(h2a), hub = h2u(h2b);
            unsigned int HA[32], HB[32];
            #pragma unroll
            for (int j = 0; j < 32; j++) {
                HA[j] = __shfl_sync(FULL_MASK, hua, j);
                HB[j] = __shfl_sync(FULL_MASK, hub, j);
            }

            // ======== stream 1 matvec: 4 chains/gate, depth 8 ========
            // r/z chain0 init = folded x-side; n chain0 init = h-side bias.
            __half2 ar0 = __hfma2(xta, wir2, cr2);
            __half2 az0 = __hfma2(xta, wiz2, cz2);
            __half2 an0 = __hfma2(wn[0], u2h(HA[0]), cnh2);
            __half2 ar1 = __hmul2(wr[1], u2h(HA[1]));
            __half2 az1 = __hmul2(wz[1], u2h(HA[1]));
            __half2 an1 = __hmul2(wn[1], u2h(HA[1]));
            __half2 ar2 = __hmul2(wr[2], u2h(HA[2]));
            __half2 az2 = __hmul2(wz[2], u2h(HA[2]));
            __half2 an2 = __hmul2(wn[2], u2h(HA[2]));
            __half2 ar3 = __hmul2(wr[3], u2h(HA[3]));
            __half2 az3 = __hmul2(wz[3], u2h(HA[3]));
            __half2 an3 = __hmul2(wn[3], u2h(HA[3]));
            ar0 = __hfma2(wr[0], u2h(HA[0]), ar0);
            az0 = __hfma2(wz[0], u2h(HA[0]), az0);
            // ======== stream 2 matvec ========
            __half2 br0 = __hfma2(xtb, wir2, cr2);
            __half2 bz0 = __hfma2(xtb, wiz2, cz2);
            __half2 bn0 = __hfma2(wn[0], u2h(HB[0]), cnh2);
            __half2 br1 = __hmul2(wr[1], u2h(HB[1]));
            __half2 bz1 = __hmul2(wz[1], u2h(HB[1]));
            __half2 bn1 = __hmul2(wn[1], u2h(HB[1]));
            __half2 br2 = __hmul2(wr[2], u2h(HB[2]));
            __half2 bz2 = __hmul2(wz[2], u2h(HB[2]));
            __half2 bn2 = __hmul2(wn[2], u2h(HB[2]));
            __half2 br3 = __hmul2(wr[3], u2h(HB[3]));
            __half2 bz3 = __hmul2(wz[3], u2h(HB[3]));
            __half2 bn3 = __hmul2(wn[3], u2h(HB[3]));
            br0 = __hfma2(wr[0], u2h(HB[0]), br0);
            bz0 = __hfma2(wz[0], u2h(HB[0]), bz0);

            #pragma unroll
            for (int j = 4; j < 32; j += 4) {
                __half2 a0 = u2h(HA[j]),   a1 = u2h(HA[j+1]);
                __half2 a2 = u2h(HA[j+2]), a3 = u2h(HA[j+3]);
                __half2 c0 = u2h(HB[j]),   c1 = u2h(HB[j+1]);
                __half2 c2 = u2h(HB[j+2]), c3 = u2h(HB[j+3]);
                ar0 = __hfma2(wr[j],   a0, ar0);
                ar1 = __hfma2(wr[j+1], a1, ar1);
                ar2 = __hfma2(wr[j+2], a2, ar2);
                ar3 = __hfma2(wr[j+3], a3, ar3);
                az0 = __hfma2(wz[j],   a0, az0);
                az1 = __hfma2(wz[j+1], a1, az1);
                az2 = __hfma2(wz[j+2], a2, az2);
                az3 = __hfma2(wz[j+3], a3, az3);
                an0 = __hfma2(wn[j],   a0, an0);
                an1 = __hfma2(wn[j+1], a1, an1);
                an2 = __hfma2(wn[j+2], a2, an2);
                an3 = __hfma2(wn[j+3], a3, an3);
                br0 = __hfma2(wr[j],   c0, br0);
                br1 = __hfma2(wr[j+1], c1, br1);
                br2 = __hfma2(wr[j+2], c2, br2);
                br3 = __hfma2(wr[j+3], c3, br3);
                bz0 = __hfma2(wz[j],   c0, bz0);
                bz1 = __hfma2(wz[j+1], c1, bz1);
                bz2 = __hfma2(wz[j+2], c2, bz2);
                bz3 = __hfma2(wz[j+3], c3, bz3);
                bn0 = __hfma2(wn[j],   c0, bn0);
                bn1 = __hfma2(wn[j+1], c1, bn1);
                bn2 = __hfma2(wn[j+2], c2, bn2);
                bn3 = __hfma2(wn[j+3], c3, bn3);
            }

            // ======== stream 1 tail ========
            {
                __half2 pre_r = __hadd2(__hadd2(ar0, ar1), __hadd2(ar2, ar3));
                __half2 pre_z = __hadd2(__hadd2(az0, az1), __hadd2(az2, az3));
                __half2 hn2   = __hadd2(__hadd2(an0, an1), __hadd2(an2, an3));
                __half2 rg = __hfma2(htanh2(pre_r), hlf2, hlf2);
                __half2 zg = __hfma2(htanh2(pre_z), hlf2, hlf2);
                __half2 xn2 = __hfma2(xta, win2, cnx2);
                __half2 ng = htanh2(__hfma2(rg, hn2, xn2));
                h2a = __hfma2(zg, __hsub2(h2a, ng), ng);
            }
            // ======== stream 2 tail ========
            {
                __half2 pre_r = __hadd2(__hadd2(br0, br1), __hadd2(br2, br3));
                __half2 pre_z = __hadd2(__hadd2(bz0, bz1), __hadd2(bz2, bz3));
                __half2 hn2   = __hadd2(__hadd2(bn0, bn1), __hadd2(bn2, bn3));
                __half2 rg = __hfma2(htanh2(pre_r), hlf2, hlf2);
                __half2 zg = __hfma2(htanh2(pre_z), hlf2, hlf2);
                __half2 xn2 = __hfma2(xtb, win2, cnx2);
                __half2 ng = htanh2(__hfma2(rg, hn2, xn2));
                h2b = __hfma2(zg, __hsub2(h2b, ng), ng);
            }
        }
    }

    // Head: out[b][o] = sum_i h_i * head_w[o][i] + head_b[o]  (fp32)
    float2 fa = __half22float2(h2a);
    float2 fb = __half22float2(h2b);
    float w0 = head_w[i], w1 = head_w[32 + i];
    float p[8] = { fa.x * w0, fa.x * w1, fa.y * w0, fa.y * w1,
                   fb.x * w0, fb.x * w1, fb.y * w0, fb.y * w1 };
    #pragma unroll
    for (int m = 16; m > 0; m >>= 1) {
        #pragma unroll
        for (int q = 0; q < 8; q++)
            p[q] += __shfl_xor_sync(FULL_MASK, p[q], m);
    }
    if (i == 0) {
        #pragma unroll
        for (int q = 0; q < 8; q++)
            out[2 * b0 + q] = p[q] + head_b[q & 1];
    }
}

extern "C" void kernel_launch(void* const* d_in, const int* in_sizes, int n_in,
                              void* d_out, int out_size) {
    const float* x      = (const float*)d_in[0];
    const float* w_ih   = (const float*)d_in[1];
    const float* w_hh   = (const float*)d_in[2];
    const float* b_ih   = (const float*)d_in[3];
    const float* b_hh   = (const float*)d_in[4];
    const float* head_w = (const float*)d_in[5];
    const float* head_b = (const float*)d_in[6];
    float* out = (float*)d_out;

    const int B = out_size / 2;           // 2048
    const int T = in_sizes[0] / B;        // 2048

    gru_kernel<<<B / 4, 32>>>(x, w_ih, w_hh, b_ih, b_hh, head_w, head_b, out, B, T);
}

// round 9
// speedup vs baseline: 2.0808x; 2.0808x over previous
#include <cuda_runtime.h>
#include <cuda_fp16.h>

// SimpleGRU: B=2048, T=2048, H=32, scalar input.
// One warp = two batch elements; lane i = hidden unit i of both.
// Interleaved-batch packing: state h2 = {hA_i, hB_i} half2; weights {w,w}.
// __launch_bounds__(32, 1): let ptxas keep all 96 weight half2s in registers
// (prior builds silently spilled ~60 regs to local -> LDL every step).
// x-side folded into r/z chain-0 inits. Sigmoid via tanh.approx.f16x2.
// h broadcast via double-buffered smem (1 STS.32 + 1 syncwarp + 8 LDS.128).

#define FULL_MASK 0xffffffffu

__device__ __forceinline__ __half2 htanh2(__half2 a) {
    unsigned int d, s = *reinterpret_cast<unsigned int*>(&a);
    asm("tanh.approx.f16x2 %0, %1;" : "=r"(d) : "r"(s));
    return *reinterpret_cast<__half2*>(&d);
}
__device__ __forceinline__ __half2 u2h(unsigned int u) {
    return *reinterpret_cast<const __half2*>(&u);
}
__device__ __forceinline__ unsigned int h2u(__half2 h) {
    return *reinterpret_cast<unsigned int*>(&h);
}

__global__ void __launch_bounds__(32, 1)
gru_kernel(const float* __restrict__ x,
           const float* __restrict__ w_ih,
           const float* __restrict__ w_hh,
           const float* __restrict__ b_ih,
           const float* __restrict__ b_hh,
           const float* __restrict__ head_w,
           const float* __restrict__ head_b,
           float* __restrict__ out,
           int B, int T)
{
    const int b0 = blockIdx.x * 2;          // two batch elements per warp
    const int i  = threadIdx.x;             // lane == hidden unit, H == 32

    // [parity][unit j] -> packed {hA_j, hB_j}
    __shared__ __align__(16) unsigned int hsh[2][32];

    // Duplicated {w,w} W_hh rows for unit i; r,z prescaled by 0.5.
    __half2 wr[32], wz[32], wn[32];
    {
        const float* Wr = w_hh + (0  + i) * 32;
        const float* Wz = w_hh + (32 + i) * 32;
        const float* Wn = w_hh + (64 + i) * 32;
        #pragma unroll
        for (int j = 0; j < 32; j++) {
            wr[j] = __float2half2_rn(Wr[j] * 0.5f);
            wz[j] = __float2half2_rn(Wz[j] * 0.5f);
            wn[j] = __float2half2_rn(Wn[j]);
        }
    }

    // x-side constants, duplicated into both lanes.
    const __half2 wir2 = __float2half2_rn(w_ih[i]      * 0.5f);
    const __half2 cr2  = __float2half2_rn((b_ih[i]      + b_hh[i])      * 0.5f);
    const __half2 wiz2 = __float2half2_rn(w_ih[32 + i] * 0.5f);
    const __half2 cz2  = __float2half2_rn((b_ih[32 + i] + b_hh[32 + i]) * 0.5f);
    const __half2 win2 = __float2half2_rn(w_ih[64 + i]);
    const __half2 cnx2 = __float2half2_rn(b_ih[64 + i]);
    const __half2 cnh2 = __float2half2_rn(b_hh[64 + i]);
    const __half2 hlf2 = __float2half2_rn(0.5f);

    __half2 h2 = __float2half2_rn(0.0f);    // packed state {hA_i, hB_i}
    const float* xA = x + (long long)b0 * T;
    const float* xB = xA + T;

    for (int t0 = 0; t0 < T; t0 += 32) {
        unsigned int xp = h2u(__floats2half2_rn(xA[t0 + i], xB[t0 + i]));
        #pragma unroll 4
        for (int k = 0; k < 32; k++) {
            __half2 xt2 = u2h(__shfl_sync(FULL_MASK, xp, k));
            const int p = k & 1;            // buffer parity

            hsh[p][i] = h2u(h2);            // one raw STS.32
            __syncwarp();                   // visible; WAR safe via parity

            // 8x LDS.128 broadcast: all 32 packed h pairs.
            const uint4* hp = (const uint4*)&hsh[p][0];
            uint4 q0 = hp[0], q1 = hp[1], q2 = hp[2], q3 = hp[3];
            uint4 q4 = hp[4], q5 = hp[5], q6 = hp[6], q7 = hp[7];
            unsigned int H[32] = {q0.x,q0.y,q0.z,q0.w, q1.x,q1.y,q1.z,q1.w,
                                  q2.x,q2.y,q2.z,q2.w, q3.x,q3.y,q3.z,q3.w,
                                  q4.x,q4.y,q4.z,q4.w, q5.x,q5.y,q5.z,q5.w,
                                  q6.x,q6.y,q6.z,q6.w, q7.x,q7.y,q7.z,q7.w};

            // Matvec: 4 chains per gate (depth 8), accumulators packed {A,B}.
            // r/z chain0 init = folded x-side; n chain0 init = h-side bias.
            __half2 r0 = __hfma2(xt2, wir2, cr2);
            __half2 z0 = __hfma2(xt2, wiz2, cz2);
            __half2 n0 = __hfma2(wn[0], u2h(H[0]), cnh2);
            __half2 r1 = __hmul2(wr[1], u2h(H[1]));
            __half2 z1 = __hmul2(wz[1], u2h(H[1]));
            __half2 n1 = __hmul2(wn[1], u2h(H[1]));
            __half2 r2_ = __hmul2(wr[2], u2h(H[2]));
            __half2 z2_ = __hmul2(wz[2], u2h(H[2]));
            __half2 n2_ = __hmul2(wn[2], u2h(H[2]));
            __half2 r3 = __hmul2(wr[3], u2h(H[3]));
            __half2 z3 = __hmul2(wz[3], u2h(H[3]));
            __half2 n3 = __hmul2(wn[3], u2h(H[3]));
            r0 = __hfma2(wr[0], u2h(H[0]), r0);
            z0 = __hfma2(wz[0], u2h(H[0]), z0);
            #pragma unroll
            for (int j = 4; j < 32; j += 4) {
                __half2 g0 = u2h(H[j]),   g1 = u2h(H[j+1]);
                __half2 g2 = u2h(H[j+2]), g3 = u2h(H[j+3]);
                r0  = __hfma2(wr[j],   g0, r0);
                r1  = __hfma2(wr[j+1], g1, r1);
                r2_ = __hfma2(wr[j+2], g2, r2_);
                r3  = __hfma2(wr[j+3], g3, r3);
                z0  = __hfma2(wz[j],   g0, z0);
                z1  = __hfma2(wz[j+1], g1, z1);
                z2_ = __hfma2(wz[j+2], g2, z2_);
                z3  = __hfma2(wz[j+3], g3, z3);
                n0  = __hfma2(wn[j],   g0, n0);
                n1  = __hfma2(wn[j+1], g1, n1);
                n2_ = __hfma2(wn[j+2], g2, n2_);
                n3  = __hfma2(wn[j+3], g3, n3);
            }
            __half2 pre_r = __hadd2(__hadd2(r0, r1), __hadd2(r2_, r3));
            __half2 pre_z = __hadd2(__hadd2(z0, z1), __hadd2(z2_, z3));
            __half2 hn2   = __hadd2(__hadd2(n0, n1), __hadd2(n2_, n3));

            // Packed gate math over {A, B}.
            __half2 rg = __hfma2(htanh2(pre_r), hlf2, hlf2);   // sigmoid
            __half2 zg = __hfma2(htanh2(pre_z), hlf2, hlf2);
            __half2 narg = __hfma2(rg, hn2, __hfma2(xt2, win2, cnx2));
            __half2 ng = htanh2(narg);

            h2 = __hfma2(zg, __hsub2(h2, ng), ng);   // (1-z)*n + z*h, packed
        }
    }

    // Head: out[b][o] = sum_i h_i * head_w[o][i] + head_b[o]  (fp32)
    float2 hf = __half22float2(h2);
    float ha = hf.x, hb = hf.y;
    float p0a = ha * head_w[i], p1a = ha * head_w[32 + i];
    float p0b = hb * head_w[i], p1b = hb * head_w[32 + i];
    #pragma unroll
    for (int m = 16; m > 0; m >>= 1) {
        p0a += __shfl_xor_sync(FULL_MASK, p0a, m);
        p1a += __shfl_xor_sync(FULL_MASK, p1a, m);
        p0b += __shfl_xor_sync(FULL_MASK, p0b, m);
        p1b += __shfl_xor_sync(FULL_MASK, p1b, m);
    }
    if (i == 0) {
        out[2 * b0]     = p0a + head_b[0];
        out[2 * b0 + 1] = p1a + head_b[1];
        out[2 * b0 + 2] = p0b + head_b[0];
        out[2 * b0 + 3] = p1b + head_b[1];
    }
}

extern "C" void kernel_launch(void* const* d_in, const int* in_sizes, int n_in,
                              void* d_out, int out_size) {
    const float* x      = (const float*)d_in[0];
    const float* w_ih   = (const float*)d_in[1];
    const float* w_hh   = (const float*)d_in[2];
    const float* b_ih   = (const float*)d_in[3];
    const float* b_hh   = (const float*)d_in[4];
    const float* head_w = (const float*)d_in[5];
    const float* head_b = (const float*)d_in[6];
    float* out = (float*)d_out;

    const int B = out_size / 2;           // 2048
    const int T = in_sizes[0] / B;        // 2048

    gru_kernel<<<B / 2, 32>>>(x, w_ih, w_hh, b_ih, b_hh, head_w, head_b, out, B, T);
}